// round 10
// baseline (speedup 1.0000x reference)
#include <cuda_runtime.h>
#include <cuda_fp16.h>
#include <math.h>
#include <stdint.h>

#define N_OBJ   128
#define HW      36864      // 192*192
#define CLSD    128
#define POSD    64
#define NCLS    80
#define TP      64         // pixels per block tile (main)
#define GRIDM   (HW / TP)  // 576 blocks; 4 CTAs/SM -> 592 slots -> 1 wave
#define ROWA    272        // A row stride bytes (17 x 16B -> LDSM conflict-free)
#define ROWB    144        // B row stride bytes (9 x 16B -> conflict-free)
#define A_BYTES (128 * ROWA)   // 34816
#define B_BYTES (128 * ROWB)   // 18432

// -------- scratch (__device__ globals) --------------------------------------
__device__ __half g_rel[N_OBJ * N_OBJ];    // relation_score fp16, [n][m]

__device__ __forceinline__ float fsig(float x) {   // sigmoid via single MUFU
    float t;
    asm("tanh.approx.f32 %0, %1;" : "=f"(t) : "f"(0.5f * x));
    return fmaf(0.5f, t, 0.5f);
}
__device__ __forceinline__ uint32_t smem_u32(const void* p) {
    uint32_t a;
    asm("{ .reg .u64 t; cvta.to.shared.u64 t, %1; cvt.u32.u64 %0, t; }" : "=r"(a) : "l"(p));
    return a;
}
__device__ __forceinline__ void ldmx4(uint32_t r[4], uint32_t addr) {
    asm volatile("ldmatrix.sync.aligned.m8n8.x4.shared.b16 {%0,%1,%2,%3}, [%4];"
        : "=r"(r[0]), "=r"(r[1]), "=r"(r[2]), "=r"(r[3]) : "r"(addr));
}
__device__ __forceinline__ void ldmx2t(uint32_t r[2], uint32_t addr) {
    asm volatile("ldmatrix.sync.aligned.m8n8.x2.trans.shared.b16 {%0,%1}, [%2];"
        : "=r"(r[0]), "=r"(r[1]) : "r"(addr));
}
__device__ __forceinline__ void mma_fp16(float c[4], const uint32_t a[4], const uint32_t b[2]) {
    asm volatile(
        "mma.sync.aligned.m16n8k16.row.col.f32.f16.f16.f32 "
        "{%0,%1,%2,%3}, {%4,%5,%6,%7}, {%8,%9}, {%0,%1,%2,%3};"
        : "+f"(c[0]), "+f"(c[1]), "+f"(c[2]), "+f"(c[3])
        : "r"(a[0]), "r"(a[1]), "r"(a[2]), "r"(a[3]), "r"(b[0]), "r"(b[1]));
}

// ============================================================================
// Kernel 1 (fused ttab + score + rel). Unchanged from 18.9us baseline.
// ============================================================================
__global__ void __launch_bounds__(128)
score_rel_kernel(const float* __restrict__ bbox,
                 const float* __restrict__ W_U,
                 const float* __restrict__ W_V,
                 const float* __restrict__ W_pos,
                 const float* __restrict__ W_P,
                 const int*   __restrict__ cls_idx)
{
    const int n    = blockIdx.x;
    const int m    = threadIdx.x;
    const int wid  = m >> 5;
    const int lane = m & 31;

    __shared__ __align__(16) float uP[CLSD];
    __shared__ __align__(16) float pv[CLSD];
    __shared__ float Trow[NCLS];
    __shared__ float Tcol[NCLS];
    __shared__ float wpos_s[4][POSD];
    __shared__ float wp2[POSD];
    __shared__ int   scls[N_OBJ];

    const int cn = cls_idx[n] - 1;

    {
        const float wpk = W_P[m];
        uP[m] = fmaxf(W_U[cn * CLSD + m], 0.0f) * wpk;
        pv[m] = wpk * fmaxf(W_V[cn * CLSD + m], 0.0f);
        scls[m] = cls_idx[m] - 1;
        if (m < POSD) {
            wp2[m] = W_P[CLSD + m];
            wpos_s[0][m] = W_pos[0 * POSD + m];
            wpos_s[1][m] = W_pos[1 * POSD + m];
            wpos_s[2][m] = W_pos[2 * POSD + m];
            wpos_s[3][m] = W_pos[3 * POSD + m];
        }
    }
    __syncthreads();

    {
        const float4 u4 = *(const float4*)&uP[lane * 4];
        const float4 p4 = *(const float4*)&pv[lane * 4];
#pragma unroll
        for (int it = 0; it < NCLS / 4; it++) {
            const int c = wid * (NCLS / 4) + it;
            float4 v = *(const float4*)&W_V[c * CLSD + lane * 4];
            float4 u = *(const float4*)&W_U[c * CLSD + lane * 4];
            float a1 = fmaxf(v.x, 0.0f) * u4.x + fmaxf(v.y, 0.0f) * u4.y
                     + fmaxf(v.z, 0.0f) * u4.z + fmaxf(v.w, 0.0f) * u4.w;
            float a2 = fmaxf(u.x, 0.0f) * p4.x + fmaxf(u.y, 0.0f) * p4.y
                     + fmaxf(u.z, 0.0f) * p4.z + fmaxf(u.w, 0.0f) * p4.w;
#pragma unroll
            for (int o = 16; o > 0; o >>= 1) {
                a1 += __shfl_xor_sync(0xFFFFFFFFu, a1, o);
                a2 += __shfl_xor_sync(0xFFFFFFFFu, a2, o);
            }
            if (lane == 0) { Trow[c] = a1; Tcol[c] = a2; }
        }
    }
    __syncthreads();

    const float4 bn = *(const float4*)&bbox[n * 4];
    const float4 bm = *(const float4*)&bbox[m * 4];
    const float wn = bn.z - bn.x, hn = bn.w - bn.y;
    const float wm = bm.z - bm.x, hm = bm.w - bm.y;
    const float xcn = 0.5f * (bn.x + bn.z), ycn = 0.5f * (bn.y + bn.w);
    const float xcm = 0.5f * (bm.x + bm.z), ycm = 0.5f * (bm.y + bm.w);

    const float dx1 = __fdividef(xcm - xcn, wn);
    const float dy1 = __fdividef(ycm - ycn, hn);
    const float dw1 = __logf(__fdividef(wm, wn));
    const float dh1 = __logf(__fdividef(hm, hn));
    const float dx2 = __fdividef(xcn - xcm, wm);
    const float dy2 = __fdividef(ycn - ycm, hm);
    const float dw2 = -dw1;
    const float dh2 = -dh1;

    float p1 = 0.0f, p2 = 0.0f;
#pragma unroll 8
    for (int d = 0; d < POSD; d++) {
        const float w0 = wpos_s[0][d], w1 = wpos_s[1][d],
                    w2 = wpos_s[2][d], w3 = wpos_s[3][d], wp = wp2[d];
        float t1 = dx1 * w0 + dy1 * w1 + dw1 * w2 + dh1 * w3;
        float t2 = dx2 * w0 + dy2 * w1 + dw2 * w2 + dh2 * w3;
        p1 += fmaxf(t1, 0.0f) * wp;
        p2 += fmaxf(t2, 0.0f) * wp;
    }

    const int cm = scls[m];
    const float r = fmaxf(fsig(Trow[cm] + p1) - fsig(Tcol[cm] + p2), 0.0f);
    g_rel[n * N_OBJ + m] = __float2half_rn(r);
}

// ============================================================================
// Kernel 2: main GEMM. 64-pixel tile, 128 threads, 4 CTAs/SM.
// smem: A = rel [n][m] fp16 (128 x 272B), B = sigmoid(L) [m][p] fp16 (128 x 144B)
// Staging sigmoid via tanh.approx.f16x2 (2 per MUFU op);
// epilogue reuses fp16 sigma from smB (zero epilogue MUFU).
// ============================================================================
__global__ void __launch_bounds__(128, 4)
main_kernel(const float* __restrict__ L, float* __restrict__ out)
{
    extern __shared__ __align__(128) char sm[];
    char* smA = sm;
    char* smB = sm + A_BYTES;

    const int tid  = threadIdx.x;
    const int wid  = tid >> 5;
    const int lane = tid & 31;
    const int P    = blockIdx.x * TP;

    // ---- stage B: sigmoid(L) fp16 [m][p], tanh.approx.f16x2 ----------------
    {
        const __half2 c05 = __floats2half2_rn(0.5f, 0.5f);
#pragma unroll
        for (int e = 0; e < 32; e++) {
            int idx = tid + e * 128;          // half2 index, 4096 total
            int mm = idx >> 5, pp = idx & 31; // one row per warp, coalesced 256B
            float2 l2 = *(const float2*)&L[(size_t)mm * HW + P + pp * 2];
            __half2 h = __floats2half2_rn(0.5f * l2.x, 0.5f * l2.y);
            uint32_t hu = *(uint32_t*)&h, tu;
            asm("tanh.approx.f16x2 %0, %1;" : "=r"(tu) : "r"(hu));
            __half2 t = *(__half2*)&tu;
            *(__half2*)(smB + mm * ROWB + pp * 4) = __hfma2(t, c05, c05);
        }
    }
    // ---- stage A (rel fp16): uint4 copies -----------------------------------
    {
        const uint4* __restrict__ rr = (const uint4*)g_rel;   // 2048 uint4
#pragma unroll
        for (int e = 0; e < 16; e++) {
            int idx = tid + e * 128;
            int nn = idx >> 4, mq = idx & 15;                 // 16 uint4 per row
            *(uint4*)(smA + nn * ROWA + mq * 16) = rr[idx];
        }
    }
    __syncthreads();

    // ---- warp tiling: 4 warps, warp = 32n x 64p -----------------------------
    const int nb = wid * 32;

    float acc[2][8][4];
#pragma unroll
    for (int a = 0; a < 2; a++)
#pragma unroll
        for (int b = 0; b < 8; b++)
#pragma unroll
            for (int q = 0; q < 4; q++) acc[a][b][q] = 0.0f;

    const int a_grp = lane >> 3;
    const int a_row = (a_grp & 1) * 8 + (lane & 7);
    const int a_col = (a_grp >> 1) * 8;
    const int b_row = lane & 15;

    const uint32_t uA = smem_u32(smA);
    const uint32_t uB = smem_u32(smB);

#pragma unroll
    for (int kc = 0; kc < 8; kc++) {
        const int k0 = kc * 16;
        uint32_t Af[2][4];
#pragma unroll
        for (int a = 0; a < 2; a++)
            ldmx4(Af[a], uA + (uint32_t)((nb + a * 16 + a_row) * ROWA + (k0 + a_col) * 2));
        uint32_t Bf[8][2];
#pragma unroll
        for (int b = 0; b < 8; b++)
            ldmx2t(Bf[b], uB + (uint32_t)((k0 + b_row) * ROWB + b * 16));
#pragma unroll
        for (int a = 0; a < 2; a++)
#pragma unroll
            for (int b = 0; b < 8; b++)
                mma_fp16(acc[a][b], Af[a], Bf[b]);
    }

    // ---- epilogue: out = L * (1 - sigma_smem * w), no MUFU ------------------
    const int g = lane >> 2, t4 = lane & 3;
#pragma unroll
    for (int a = 0; a < 2; a++) {
#pragma unroll
        for (int b = 0; b < 8; b++) {
            const int n0 = nb + a * 16 + g;
            const int pl = b * 8 + 2 * t4;      // local pixel (even)
            const int p0 = P + pl;
            {
                size_t off = (size_t)n0 * HW + p0;
                float2 lv = *(const float2*)&L[off];
                float2 sf = __half22float2(*(const __half2*)(smB + n0 * ROWB + pl * 2));
                float2 ov;
                ov.x = lv.x * (1.0f - sf.x * acc[a][b][0]);
                ov.y = lv.y * (1.0f - sf.y * acc[a][b][1]);
                *(float2*)&out[off] = ov;
            }
            {
                size_t off = (size_t)(n0 + 8) * HW + p0;
                float2 lv = *(const float2*)&L[off];
                float2 sf = __half22float2(*(const __half2*)(smB + (n0 + 8) * ROWB + pl * 2));
                float2 ov;
                ov.x = lv.x * (1.0f - sf.x * acc[a][b][2]);
                ov.y = lv.y * (1.0f - sf.y * acc[a][b][3]);
                *(float2*)&out[off] = ov;
            }
        }
    }
}

// ============================================================================
extern "C" void kernel_launch(void* const* d_in, const int* in_sizes, int n_in,
                              void* d_out, int out_size)
{
    const float* L     = (const float*)d_in[0];   // mask_logits (1,128,192,192)
    const float* bbox  = (const float*)d_in[1];   // (128,4)
    const float* W_U   = (const float*)d_in[2];   // (80,128)
    const float* W_V   = (const float*)d_in[3];   // (80,128)
    const float* W_pos = (const float*)d_in[4];   // (4,64)
    const float* W_P   = (const float*)d_in[5];   // (192,1)
    const int*   cls   = (const int*)d_in[6];     // (128,)
    float* out = (float*)d_out;

    const int dyn_smem = A_BYTES + B_BYTES;       // 53248 B -> 4 CTAs/SM
    cudaFuncSetAttribute(main_kernel,
                         cudaFuncAttributeMaxDynamicSharedMemorySize, dyn_smem);

    score_rel_kernel<<<N_OBJ, N_OBJ>>>(bbox, W_U, W_V, W_pos, W_P, cls);
    main_kernel<<<GRIDM, 128, dyn_smem>>>(L, out);
}

// round 11
// speedup vs baseline: 1.1102x; 1.1102x over previous
#include <cuda_runtime.h>
#include <cuda_fp16.h>
#include <math.h>
#include <stdint.h>

#define N_OBJ   128
#define HW      36864      // 192*192
#define CLSD    128
#define POSD    64
#define NCLS    80
#define TP      128        // pixels per block tile (main)
#define GRIDM   (HW / TP)  // 288 blocks; occ 2/SM -> 296 slots -> 1 wave
#define ROWA    272        // fp16 row stride bytes (17 x 16B -> LDSM conflict-free)
#define ROWB    272
#define A_BYTES (128 * ROWA)   // 34816
#define B_BYTES (128 * ROWB)   // 34816

// -------- scratch (__device__ globals) --------------------------------------
__device__ __half g_rel[N_OBJ * N_OBJ];    // relation_score fp16, [n][m]

__device__ __forceinline__ float fsig(float x) {   // sigmoid via single MUFU
    float t;
    asm("tanh.approx.f32 %0, %1;" : "=f"(t) : "f"(0.5f * x));
    return fmaf(0.5f, t, 0.5f);
}
__device__ __forceinline__ uint32_t smem_u32(const void* p) {
    uint32_t a;
    asm("{ .reg .u64 t; cvta.to.shared.u64 t, %1; cvt.u32.u64 %0, t; }" : "=r"(a) : "l"(p));
    return a;
}
__device__ __forceinline__ void ldmx4(uint32_t r[4], uint32_t addr) {
    asm volatile("ldmatrix.sync.aligned.m8n8.x4.shared.b16 {%0,%1,%2,%3}, [%4];"
        : "=r"(r[0]), "=r"(r[1]), "=r"(r[2]), "=r"(r[3]) : "r"(addr));
}
__device__ __forceinline__ void ldmx2t(uint32_t r[2], uint32_t addr) {
    asm volatile("ldmatrix.sync.aligned.m8n8.x2.trans.shared.b16 {%0,%1}, [%2];"
        : "=r"(r[0]), "=r"(r[1]) : "r"(addr));
}
__device__ __forceinline__ void mma_fp16(float c[4], const uint32_t a[4], const uint32_t b[2]) {
    asm volatile(
        "mma.sync.aligned.m16n8k16.row.col.f32.f16.f16.f32 "
        "{%0,%1,%2,%3}, {%4,%5,%6,%7}, {%8,%9}, {%0,%1,%2,%3};"
        : "+f"(c[0]), "+f"(c[1]), "+f"(c[2]), "+f"(c[3])
        : "r"(a[0]), "r"(a[1]), "r"(a[2]), "r"(a[3]), "r"(b[0]), "r"(b[1]));
}
// sigmoid of 2 floats -> packed half2, single MUFU (f16x2 tanh)
__device__ __forceinline__ uint32_t sig2_h2(float x, float y) {
    __half2 h = __floats2half2_rn(0.5f * x, 0.5f * y);
    uint32_t hu = *(uint32_t*)&h, tu;
    asm("tanh.approx.f16x2 %0, %1;" : "=r"(tu) : "r"(hu));
    const __half2 c05 = __floats2half2_rn(0.5f, 0.5f);
    __half2 t = *(__half2*)&tu;
    __half2 r = __hfma2(t, c05, c05);
    return *(uint32_t*)&r;
}

// ============================================================================
// Kernel 1 (fused ttab + score + rel). Unchanged (proven, 18.9us baseline).
// ============================================================================
__global__ void __launch_bounds__(128)
score_rel_kernel(const float* __restrict__ bbox,
                 const float* __restrict__ W_U,
                 const float* __restrict__ W_V,
                 const float* __restrict__ W_pos,
                 const float* __restrict__ W_P,
                 const int*   __restrict__ cls_idx)
{
    const int n    = blockIdx.x;
    const int m    = threadIdx.x;
    const int wid  = m >> 5;
    const int lane = m & 31;

    __shared__ __align__(16) float uP[CLSD];
    __shared__ __align__(16) float pv[CLSD];
    __shared__ float Trow[NCLS];
    __shared__ float Tcol[NCLS];
    __shared__ float wpos_s[4][POSD];
    __shared__ float wp2[POSD];
    __shared__ int   scls[N_OBJ];

    const int cn = cls_idx[n] - 1;

    {
        const float wpk = W_P[m];
        uP[m] = fmaxf(W_U[cn * CLSD + m], 0.0f) * wpk;
        pv[m] = wpk * fmaxf(W_V[cn * CLSD + m], 0.0f);
        scls[m] = cls_idx[m] - 1;
        if (m < POSD) {
            wp2[m] = W_P[CLSD + m];
            wpos_s[0][m] = W_pos[0 * POSD + m];
            wpos_s[1][m] = W_pos[1 * POSD + m];
            wpos_s[2][m] = W_pos[2 * POSD + m];
            wpos_s[3][m] = W_pos[3 * POSD + m];
        }
    }
    __syncthreads();

    {
        const float4 u4 = *(const float4*)&uP[lane * 4];
        const float4 p4 = *(const float4*)&pv[lane * 4];
#pragma unroll
        for (int it = 0; it < NCLS / 4; it++) {
            const int c = wid * (NCLS / 4) + it;
            float4 v = *(const float4*)&W_V[c * CLSD + lane * 4];
            float4 u = *(const float4*)&W_U[c * CLSD + lane * 4];
            float a1 = fmaxf(v.x, 0.0f) * u4.x + fmaxf(v.y, 0.0f) * u4.y
                     + fmaxf(v.z, 0.0f) * u4.z + fmaxf(v.w, 0.0f) * u4.w;
            float a2 = fmaxf(u.x, 0.0f) * p4.x + fmaxf(u.y, 0.0f) * p4.y
                     + fmaxf(u.z, 0.0f) * p4.z + fmaxf(u.w, 0.0f) * p4.w;
#pragma unroll
            for (int o = 16; o > 0; o >>= 1) {
                a1 += __shfl_xor_sync(0xFFFFFFFFu, a1, o);
                a2 += __shfl_xor_sync(0xFFFFFFFFu, a2, o);
            }
            if (lane == 0) { Trow[c] = a1; Tcol[c] = a2; }
        }
    }
    __syncthreads();

    const float4 bn = *(const float4*)&bbox[n * 4];
    const float4 bm = *(const float4*)&bbox[m * 4];
    const float wn = bn.z - bn.x, hn = bn.w - bn.y;
    const float wm = bm.z - bm.x, hm = bm.w - bm.y;
    const float xcn = 0.5f * (bn.x + bn.z), ycn = 0.5f * (bn.y + bn.w);
    const float xcm = 0.5f * (bm.x + bm.z), ycm = 0.5f * (bm.y + bm.w);

    const float dx1 = __fdividef(xcm - xcn, wn);
    const float dy1 = __fdividef(ycm - ycn, hn);
    const float dw1 = __logf(__fdividef(wm, wn));
    const float dh1 = __logf(__fdividef(hm, hn));
    const float dx2 = __fdividef(xcn - xcm, wm);
    const float dy2 = __fdividef(ycn - ycm, hm);
    const float dw2 = -dw1;
    const float dh2 = -dh1;

    float p1 = 0.0f, p2 = 0.0f;
#pragma unroll 8
    for (int d = 0; d < POSD; d++) {
        const float w0 = wpos_s[0][d], w1 = wpos_s[1][d],
                    w2 = wpos_s[2][d], w3 = wpos_s[3][d], wp = wp2[d];
        float t1 = dx1 * w0 + dy1 * w1 + dw1 * w2 + dh1 * w3;
        float t2 = dx2 * w0 + dy2 * w1 + dw2 * w2 + dh2 * w3;
        p1 += fmaxf(t1, 0.0f) * wp;
        p2 += fmaxf(t2, 0.0f) * wp;
    }

    const int cm = scls[m];
    const float r = fmaxf(fsig(Trow[cm] + p1) - fsig(Tcol[cm] + p2), 0.0f);
    g_rel[n * N_OBJ + m] = __float2half_rn(r);
}

// ============================================================================
// Kernel 2: main GEMM (round-8 structure). 128-pixel tile, 256 thr, 2 CTAs/SM.
// Staging: A uint4 copies; B float4 LDG + tanh.approx.f16x2 + STS.64
// (half the LDG/MUFU/STS issue count of round 8). Epilogue: fp32 sigmoid.
// ============================================================================
__global__ void __launch_bounds__(256, 2)
main_kernel(const float* __restrict__ L, float* __restrict__ out)
{
    extern __shared__ __align__(128) char sm[];
    char* smA = sm;
    char* smB = sm + A_BYTES;

    const int tid  = threadIdx.x;
    const int wid  = tid >> 5;
    const int lane = tid & 31;
    const int P    = blockIdx.x * TP;

    // ---- stage A (rel fp16): uint4 copies -----------------------------------
    {
        const uint4* __restrict__ rr = (const uint4*)g_rel;   // 2048 uint4
#pragma unroll
        for (int e = 0; e < 2048 / 256; e++) {
            int idx = tid + e * 256;
            int nn = idx >> 4, mq = idx & 15;                 // 16 uint4 per row
            *(uint4*)(smA + nn * ROWA + mq * 16) = rr[idx];
        }
    }
    // ---- stage B: sigmoid(L) fp16 [m][p]; float4 LDG + f16x2 tanh ----------
#pragma unroll
    for (int e = 0; e < 4096 / 256; e++) {
        int idx = tid + e * 256;          // float4 index (4096 total)
        int mm = idx >> 5, p4i = idx & 31;  // 32 float4 per 128-px row
        float4 l4 = *(const float4*)&L[(size_t)mm * HW + P + p4i * 4];
        uint2 s;
        s.x = sig2_h2(l4.x, l4.y);
        s.y = sig2_h2(l4.z, l4.w);
        *(uint2*)(smB + mm * ROWB + p4i * 8) = s;   // 4 halves, 8B aligned
    }
    __syncthreads();

    // ---- warp tiling: 2 n-groups x 4 p-groups; warp = n64 x p32 ------------
    const int nb = (wid >> 2) * 64;
    const int pb = (wid & 3) * 32;

    float acc[4][4][4];
#pragma unroll
    for (int a = 0; a < 4; a++)
#pragma unroll
        for (int b = 0; b < 4; b++)
#pragma unroll
            for (int q = 0; q < 4; q++) acc[a][b][q] = 0.0f;

    const int a_grp = lane >> 3;
    const int a_row = (a_grp & 1) * 8 + (lane & 7);
    const int a_col = (a_grp >> 1) * 8;
    const int b_row = lane & 15;

    const uint32_t uA = smem_u32(smA);
    const uint32_t uB = smem_u32(smB);

#pragma unroll
    for (int kc = 0; kc < 8; kc++) {
        const int k0 = kc * 16;
        uint32_t Af[4][4];
#pragma unroll
        for (int a = 0; a < 4; a++)
            ldmx4(Af[a], uA + (uint32_t)((nb + a * 16 + a_row) * ROWA + (k0 + a_col) * 2));
        uint32_t Bf[4][2];
#pragma unroll
        for (int b = 0; b < 4; b++)
            ldmx2t(Bf[b], uB + (uint32_t)((k0 + b_row) * ROWB + (pb + b * 8) * 2));
#pragma unroll
        for (int a = 0; a < 4; a++)
#pragma unroll
            for (int b = 0; b < 4; b++)
                mma_fp16(acc[a][b], Af[a], Bf[b]);
    }

    // ---- epilogue: out = L * (1 - sigmoid(L) * w), fp32 MUFU ----------------
    const int g = lane >> 2, t4 = lane & 3;
#pragma unroll
    for (int a = 0; a < 4; a++) {
#pragma unroll
        for (int b = 0; b < 4; b++) {
            const int n0 = nb + a * 16 + g;
            const int p0 = P + pb + b * 8 + 2 * t4;
            {
                size_t off = (size_t)n0 * HW + p0;
                float2 lv = *(const float2*)&L[off];
                float2 ov;
                ov.x = lv.x * (1.0f - fsig(lv.x) * acc[a][b][0]);
                ov.y = lv.y * (1.0f - fsig(lv.y) * acc[a][b][1]);
                *(float2*)&out[off] = ov;
            }
            {
                size_t off = (size_t)(n0 + 8) * HW + p0;
                float2 lv = *(const float2*)&L[off];
                float2 ov;
                ov.x = lv.x * (1.0f - fsig(lv.x) * acc[a][b][2]);
                ov.y = lv.y * (1.0f - fsig(lv.y) * acc[a][b][3]);
                *(float2*)&out[off] = ov;
            }
        }
    }
}

// ============================================================================
extern "C" void kernel_launch(void* const* d_in, const int* in_sizes, int n_in,
                              void* d_out, int out_size)
{
    const float* L     = (const float*)d_in[0];   // mask_logits (1,128,192,192)
    const float* bbox  = (const float*)d_in[1];   // (128,4)
    const float* W_U   = (const float*)d_in[2];   // (80,128)
    const float* W_V   = (const float*)d_in[3];   // (80,128)
    const float* W_pos = (const float*)d_in[4];   // (4,64)
    const float* W_P   = (const float*)d_in[5];   // (192,1)
    const int*   cls   = (const int*)d_in[6];     // (128,)
    float* out = (float*)d_out;

    const int dyn_smem = A_BYTES + B_BYTES;       // 69632 B -> 2 CTAs/SM
    cudaFuncSetAttribute(main_kernel,
                         cudaFuncAttributeMaxDynamicSharedMemorySize, dyn_smem);

    score_rel_kernel<<<N_OBJ, N_OBJ>>>(bbox, W_U, W_V, W_pos, W_P, cls);
    main_kernel<<<GRIDM, 256, dyn_smem>>>(L, out);
}

// round 12
// speedup vs baseline: 1.1252x; 1.0135x over previous
#include <cuda_runtime.h>
#include <cuda_fp16.h>
#include <math.h>
#include <stdint.h>

#define N_OBJ   128
#define HW      36864      // 192*192
#define CLSD    128
#define POSD    64
#define NCLS    80
#define TP      128        // pixels per block tile (main)
#define GRIDM   (HW / TP)  // 288 blocks; occ 2/SM -> 296 slots -> 1 wave
#define ROWA    272        // fp16 row stride bytes (17 x 16B -> LDSM conflict-free)
#define ROWB    272
#define A_BYTES (128 * ROWA)   // 34816
#define B_BYTES (128 * ROWB)   // 34816

// -------- scratch (__device__ globals) --------------------------------------
__device__ __half g_rel[N_OBJ * N_OBJ];    // relation_score fp16, [n][m]

__device__ __forceinline__ float fsig(float x) {   // sigmoid via single MUFU
    float t;
    asm("tanh.approx.f32 %0, %1;" : "=f"(t) : "f"(0.5f * x));
    return fmaf(0.5f, t, 0.5f);
}
__device__ __forceinline__ uint32_t smem_u32(const void* p) {
    uint32_t a;
    asm("{ .reg .u64 t; cvta.to.shared.u64 t, %1; cvt.u32.u64 %0, t; }" : "=r"(a) : "l"(p));
    return a;
}
__device__ __forceinline__ void ldmx4(uint32_t r[4], uint32_t addr) {
    asm volatile("ldmatrix.sync.aligned.m8n8.x4.shared.b16 {%0,%1,%2,%3}, [%4];"
        : "=r"(r[0]), "=r"(r[1]), "=r"(r[2]), "=r"(r[3]) : "r"(addr));
}
__device__ __forceinline__ void ldmx2t(uint32_t r[2], uint32_t addr) {
    asm volatile("ldmatrix.sync.aligned.m8n8.x2.trans.shared.b16 {%0,%1}, [%2];"
        : "=r"(r[0]), "=r"(r[1]) : "r"(addr));
}
__device__ __forceinline__ void mma_fp16(float c[4], const uint32_t a[4], const uint32_t b[2]) {
    asm volatile(
        "mma.sync.aligned.m16n8k16.row.col.f32.f16.f16.f32 "
        "{%0,%1,%2,%3}, {%4,%5,%6,%7}, {%8,%9}, {%0,%1,%2,%3};"
        : "+f"(c[0]), "+f"(c[1]), "+f"(c[2]), "+f"(c[3])
        : "r"(a[0]), "r"(a[1]), "r"(a[2]), "r"(a[3]), "r"(b[0]), "r"(b[1]));
}
// sigmoid of 2 floats -> packed half2, single MUFU (f16x2 tanh)
__device__ __forceinline__ uint32_t sig2_h2(float x, float y) {
    __half2 h = __floats2half2_rn(0.5f * x, 0.5f * y);
    uint32_t hu = *(uint32_t*)&h, tu;
    asm("tanh.approx.f16x2 %0, %1;" : "=r"(tu) : "r"(hu));
    const __half2 c05 = __floats2half2_rn(0.5f, 0.5f);
    __half2 t = *(__half2*)&tu;
    __half2 r = __hfma2(t, c05, c05);
    return *(uint32_t*)&r;
}

// ============================================================================
// Kernel 1 (fused ttab + score + rel). Unchanged (proven).
// ============================================================================
__global__ void __launch_bounds__(128)
score_rel_kernel(const float* __restrict__ bbox,
                 const float* __restrict__ W_U,
                 const float* __restrict__ W_V,
                 const float* __restrict__ W_pos,
                 const float* __restrict__ W_P,
                 const int*   __restrict__ cls_idx)
{
    const int n    = blockIdx.x;
    const int m    = threadIdx.x;
    const int wid  = m >> 5;
    const int lane = m & 31;

    __shared__ __align__(16) float uP[CLSD];
    __shared__ __align__(16) float pv[CLSD];
    __shared__ float Trow[NCLS];
    __shared__ float Tcol[NCLS];
    __shared__ float wpos_s[4][POSD];
    __shared__ float wp2[POSD];
    __shared__ int   scls[N_OBJ];

    const int cn = cls_idx[n] - 1;

    {
        const float wpk = W_P[m];
        uP[m] = fmaxf(W_U[cn * CLSD + m], 0.0f) * wpk;
        pv[m] = wpk * fmaxf(W_V[cn * CLSD + m], 0.0f);
        scls[m] = cls_idx[m] - 1;
        if (m < POSD) {
            wp2[m] = W_P[CLSD + m];
            wpos_s[0][m] = W_pos[0 * POSD + m];
            wpos_s[1][m] = W_pos[1 * POSD + m];
            wpos_s[2][m] = W_pos[2 * POSD + m];
            wpos_s[3][m] = W_pos[3 * POSD + m];
        }
    }
    __syncthreads();

    {
        const float4 u4 = *(const float4*)&uP[lane * 4];
        const float4 p4 = *(const float4*)&pv[lane * 4];
#pragma unroll
        for (int it = 0; it < NCLS / 4; it++) {
            const int c = wid * (NCLS / 4) + it;
            float4 v = *(const float4*)&W_V[c * CLSD + lane * 4];
            float4 u = *(const float4*)&W_U[c * CLSD + lane * 4];
            float a1 = fmaxf(v.x, 0.0f) * u4.x + fmaxf(v.y, 0.0f) * u4.y
                     + fmaxf(v.z, 0.0f) * u4.z + fmaxf(v.w, 0.0f) * u4.w;
            float a2 = fmaxf(u.x, 0.0f) * p4.x + fmaxf(u.y, 0.0f) * p4.y
                     + fmaxf(u.z, 0.0f) * p4.z + fmaxf(u.w, 0.0f) * p4.w;
#pragma unroll
            for (int o = 16; o > 0; o >>= 1) {
                a1 += __shfl_xor_sync(0xFFFFFFFFu, a1, o);
                a2 += __shfl_xor_sync(0xFFFFFFFFu, a2, o);
            }
            if (lane == 0) { Trow[c] = a1; Tcol[c] = a2; }
        }
    }
    __syncthreads();

    const float4 bn = *(const float4*)&bbox[n * 4];
    const float4 bm = *(const float4*)&bbox[m * 4];
    const float wn = bn.z - bn.x, hn = bn.w - bn.y;
    const float wm = bm.z - bm.x, hm = bm.w - bm.y;
    const float xcn = 0.5f * (bn.x + bn.z), ycn = 0.5f * (bn.y + bn.w);
    const float xcm = 0.5f * (bm.x + bm.z), ycm = 0.5f * (bm.y + bm.w);

    const float dx1 = __fdividef(xcm - xcn, wn);
    const float dy1 = __fdividef(ycm - ycn, hn);
    const float dw1 = __logf(__fdividef(wm, wn));
    const float dh1 = __logf(__fdividef(hm, hn));
    const float dx2 = __fdividef(xcn - xcm, wm);
    const float dy2 = __fdividef(ycn - ycm, hm);
    const float dw2 = -dw1;
    const float dh2 = -dh1;

    float p1 = 0.0f, p2 = 0.0f;
#pragma unroll 8
    for (int d = 0; d < POSD; d++) {
        const float w0 = wpos_s[0][d], w1 = wpos_s[1][d],
                    w2 = wpos_s[2][d], w3 = wpos_s[3][d], wp = wp2[d];
        float t1 = dx1 * w0 + dy1 * w1 + dw1 * w2 + dh1 * w3;
        float t2 = dx2 * w0 + dy2 * w1 + dw2 * w2 + dh2 * w3;
        p1 += fmaxf(t1, 0.0f) * wp;
        p2 += fmaxf(t2, 0.0f) * wp;
    }

    const int cm = scls[m];
    const float r = fmaxf(fsig(Trow[cm] + p1) - fsig(Tcol[cm] + p2), 0.0f);
    g_rel[n * N_OBJ + m] = __float2half_rn(r);
}

// ============================================================================
// Kernel 2: main GEMM, K-pipelined. Stage A + B-chunk0; then per K-chunk:
//   LDG chunk kc+1 (latency hides under MMA kc) -> MMA kc -> sig+STS kc+1 -> bar
// Epilogue: fp32 sigmoid (precision-proven), no trailing sync needed.
// ============================================================================
__global__ void __launch_bounds__(256, 2)
main_kernel(const float* __restrict__ L, float* __restrict__ out)
{
    extern __shared__ __align__(128) char sm[];
    char* smA = sm;
    char* smB = sm + A_BYTES;

    const int tid  = threadIdx.x;
    const int wid  = tid >> 5;
    const int lane = tid & 31;
    const int P    = blockIdx.x * TP;

    // per-thread B-chunk staging coords (each warp owns one row of 16/chunk,
    // covering rows (tid>>5) and (tid>>5)+8; lanes span 32 float4 = 128 px)
    const int s_row = tid >> 5;           // 0..7
    const int s_p4  = tid & 31;           // float4 index within row

    // ---- prologue: stage A fully + B chunk 0 --------------------------------
    {
        const uint4* __restrict__ rr = (const uint4*)g_rel;   // 2048 uint4
#pragma unroll
        for (int e = 0; e < 8; e++) {
            int idx = tid + e * 256;
            int nn = idx >> 4, mq = idx & 15;
            *(uint4*)(smA + nn * ROWA + mq * 16) = rr[idx];
        }
        float4 b0 = *(const float4*)&L[(size_t)s_row * HW + P + s_p4 * 4];
        float4 b1 = *(const float4*)&L[(size_t)(s_row + 8) * HW + P + s_p4 * 4];
        uint2 s0, s1;
        s0.x = sig2_h2(b0.x, b0.y);  s0.y = sig2_h2(b0.z, b0.w);
        s1.x = sig2_h2(b1.x, b1.y);  s1.y = sig2_h2(b1.z, b1.w);
        *(uint2*)(smB + s_row * ROWB + s_p4 * 8) = s0;
        *(uint2*)(smB + (s_row + 8) * ROWB + s_p4 * 8) = s1;
    }
    __syncthreads();

    // ---- warp tiling: 2 n-groups x 4 p-groups; warp = n64 x p32 ------------
    const int nb = (wid >> 2) * 64;
    const int pb = (wid & 3) * 32;

    float acc[4][4][4];
#pragma unroll
    for (int a = 0; a < 4; a++)
#pragma unroll
        for (int b = 0; b < 4; b++)
#pragma unroll
            for (int q = 0; q < 4; q++) acc[a][b][q] = 0.0f;

    const int a_grp = lane >> 3;
    const int a_row = (a_grp & 1) * 8 + (lane & 7);
    const int a_col = (a_grp >> 1) * 8;
    const int b_row = lane & 15;

    const uint32_t uA = smem_u32(smA);
    const uint32_t uB = smem_u32(smB);

#pragma unroll
    for (int kc = 0; kc < 8; kc++) {
        // ---- prefetch B chunk kc+1 (LDG issued before MMA; latency hidden) --
        float4 pf0, pf1;
        if (kc < 7) {
            const int mb = (kc + 1) * 16;
            pf0 = *(const float4*)&L[(size_t)(mb + s_row) * HW + P + s_p4 * 4];
            pf1 = *(const float4*)&L[(size_t)(mb + 8 + s_row) * HW + P + s_p4 * 4];
        }

        // ---- MMA chunk kc (reads smB rows [16kc,16kc+16), barriered) --------
        const int k0 = kc * 16;
        uint32_t Af[4][4];
#pragma unroll
        for (int a = 0; a < 4; a++)
            ldmx4(Af[a], uA + (uint32_t)((nb + a * 16 + a_row) * ROWA + (k0 + a_col) * 2));
        uint32_t Bf[4][2];
#pragma unroll
        for (int b = 0; b < 4; b++)
            ldmx2t(Bf[b], uB + (uint32_t)((k0 + b_row) * ROWB + (pb + b * 8) * 2));
#pragma unroll
        for (int a = 0; a < 4; a++)
#pragma unroll
            for (int b = 0; b < 4; b++)
                mma_fp16(acc[a][b], Af[a], Bf[b]);

        // ---- convert + store chunk kc+1, then sync for next iteration -------
        if (kc < 7) {
            const int mb = (kc + 1) * 16;
            uint2 s0, s1;
            s0.x = sig2_h2(pf0.x, pf0.y);  s0.y = sig2_h2(pf0.z, pf0.w);
            s1.x = sig2_h2(pf1.x, pf1.y);  s1.y = sig2_h2(pf1.z, pf1.w);
            *(uint2*)(smB + (mb + s_row) * ROWB + s_p4 * 8) = s0;
            *(uint2*)(smB + (mb + 8 + s_row) * ROWB + s_p4 * 8) = s1;
            __syncthreads();
        }
    }

    // ---- epilogue: out = L * (1 - sigmoid(L) * w), fp32 MUFU ----------------
    const int g = lane >> 2, t4 = lane & 3;
#pragma unroll
    for (int a = 0; a < 4; a++) {
#pragma unroll
        for (int b = 0; b < 4; b++) {
            const int n0 = nb + a * 16 + g;
            const int p0 = P + pb + b * 8 + 2 * t4;
            {
                size_t off = (size_t)n0 * HW + p0;
                float2 lv = *(const float2*)&L[off];
                float2 ov;
                ov.x = lv.x * (1.0f - fsig(lv.x) * acc[a][b][0]);
                ov.y = lv.y * (1.0f - fsig(lv.y) * acc[a][b][1]);
                *(float2*)&out[off] = ov;
            }
            {
                size_t off = (size_t)(n0 + 8) * HW + p0;
                float2 lv = *(const float2*)&L[off];
                float2 ov;
                ov.x = lv.x * (1.0f - fsig(lv.x) * acc[a][b][2]);
                ov.y = lv.y * (1.0f - fsig(lv.y) * acc[a][b][3]);
                *(float2*)&out[off] = ov;
            }
        }
    }
}

// ============================================================================
extern "C" void kernel_launch(void* const* d_in, const int* in_sizes, int n_in,
                              void* d_out, int out_size)
{
    const float* L     = (const float*)d_in[0];   // mask_logits (1,128,192,192)
    const float* bbox  = (const float*)d_in[1];   // (128,4)
    const float* W_U   = (const float*)d_in[2];   // (80,128)
    const float* W_V   = (const float*)d_in[3];   // (80,128)
    const float* W_pos = (const float*)d_in[4];   // (4,64)
    const float* W_P   = (const float*)d_in[5];   // (192,1)
    const int*   cls   = (const int*)d_in[6];     // (128,)
    float* out = (float*)d_out;

    const int dyn_smem = A_BYTES + B_BYTES;       // 69632 B -> 2 CTAs/SM
    cudaFuncSetAttribute(main_kernel,
                         cudaFuncAttributeMaxDynamicSharedMemorySize, dyn_smem);

    score_rel_kernel<<<N_OBJ, N_OBJ>>>(bbox, W_U, W_V, W_pos, W_P, cls);
    main_kernel<<<GRIDM, 256, dyn_smem>>>(L, out);
}

// round 13
// speedup vs baseline: 1.1505x; 1.0225x over previous
#include <cuda_runtime.h>
#include <cuda_fp16.h>
#include <math.h>
#include <stdint.h>

#define N_OBJ   128
#define HW      36864      // 192*192
#define CLSD    128
#define POSD    64
#define NCLS    80
#define TP      128        // pixels per block tile (main)
#define GRIDM   (HW / TP)  // 288 blocks; occ 2/SM -> 296 slots -> 1 wave
#define ROWA    272        // fp16 row stride bytes (17 x 16B -> LDSM conflict-free)
#define ROWB    272
#define ROWC    528        // fp32 C relayout row stride bytes (132 floats)
#define A_BYTES (128 * ROWA)   // 34816
#define B_BYTES (128 * ROWB)   // 34816

// -------- scratch (__device__ globals) --------------------------------------
__device__ __half g_rel[N_OBJ * N_OBJ];    // relation_score fp16, [n][m]

__device__ __forceinline__ float fsig(float x) {   // sigmoid via single MUFU
    float t;
    asm("tanh.approx.f32 %0, %1;" : "=f"(t) : "f"(0.5f * x));
    return fmaf(0.5f, t, 0.5f);
}
__device__ __forceinline__ uint32_t smem_u32(const void* p) {
    uint32_t a;
    asm("{ .reg .u64 t; cvta.to.shared.u64 t, %1; cvt.u32.u64 %0, t; }" : "=r"(a) : "l"(p));
    return a;
}
__device__ __forceinline__ void ldmx4(uint32_t r[4], uint32_t addr) {
    asm volatile("ldmatrix.sync.aligned.m8n8.x4.shared.b16 {%0,%1,%2,%3}, [%4];"
        : "=r"(r[0]), "=r"(r[1]), "=r"(r[2]), "=r"(r[3]) : "r"(addr));
}
__device__ __forceinline__ void ldmx2t(uint32_t r[2], uint32_t addr) {
    asm volatile("ldmatrix.sync.aligned.m8n8.x2.trans.shared.b16 {%0,%1}, [%2];"
        : "=r"(r[0]), "=r"(r[1]) : "r"(addr));
}
__device__ __forceinline__ void mma_fp16(float c[4], const uint32_t a[4], const uint32_t b[2]) {
    asm volatile(
        "mma.sync.aligned.m16n8k16.row.col.f32.f16.f16.f32 "
        "{%0,%1,%2,%3}, {%4,%5,%6,%7}, {%8,%9}, {%0,%1,%2,%3};"
        : "+f"(c[0]), "+f"(c[1]), "+f"(c[2]), "+f"(c[3])
        : "r"(a[0]), "r"(a[1]), "r"(a[2]), "r"(a[3]), "r"(b[0]), "r"(b[1]));
}
// sigmoid of 2 floats -> packed half2, single MUFU (f16x2 tanh)
__device__ __forceinline__ uint32_t sig2_h2(float x, float y) {
    __half2 h = __floats2half2_rn(0.5f * x, 0.5f * y);
    uint32_t hu = *(uint32_t*)&h, tu;
    asm("tanh.approx.f16x2 %0, %1;" : "=r"(tu) : "r"(hu));
    const __half2 c05 = __floats2half2_rn(0.5f, 0.5f);
    __half2 t = *(__half2*)&tu;
    __half2 r = __hfma2(t, c05, c05);
    return *(uint32_t*)&r;
}

// ============================================================================
// Kernel 1 (fused ttab + score + rel). Unchanged (proven).
// ============================================================================
__global__ void __launch_bounds__(128)
score_rel_kernel(const float* __restrict__ bbox,
                 const float* __restrict__ W_U,
                 const float* __restrict__ W_V,
                 const float* __restrict__ W_pos,
                 const float* __restrict__ W_P,
                 const int*   __restrict__ cls_idx)
{
    const int n    = blockIdx.x;
    const int m    = threadIdx.x;
    const int wid  = m >> 5;
    const int lane = m & 31;

    __shared__ __align__(16) float uP[CLSD];
    __shared__ __align__(16) float pv[CLSD];
    __shared__ float Trow[NCLS];
    __shared__ float Tcol[NCLS];
    __shared__ float wpos_s[4][POSD];
    __shared__ float wp2[POSD];
    __shared__ int   scls[N_OBJ];

    const int cn = cls_idx[n] - 1;

    {
        const float wpk = W_P[m];
        uP[m] = fmaxf(W_U[cn * CLSD + m], 0.0f) * wpk;
        pv[m] = wpk * fmaxf(W_V[cn * CLSD + m], 0.0f);
        scls[m] = cls_idx[m] - 1;
        if (m < POSD) {
            wp2[m] = W_P[CLSD + m];
            wpos_s[0][m] = W_pos[0 * POSD + m];
            wpos_s[1][m] = W_pos[1 * POSD + m];
            wpos_s[2][m] = W_pos[2 * POSD + m];
            wpos_s[3][m] = W_pos[3 * POSD + m];
        }
    }
    __syncthreads();

    {
        const float4 u4 = *(const float4*)&uP[lane * 4];
        const float4 p4 = *(const float4*)&pv[lane * 4];
#pragma unroll
        for (int it = 0; it < NCLS / 4; it++) {
            const int c = wid * (NCLS / 4) + it;
            float4 v = *(const float4*)&W_V[c * CLSD + lane * 4];
            float4 u = *(const float4*)&W_U[c * CLSD + lane * 4];
            float a1 = fmaxf(v.x, 0.0f) * u4.x + fmaxf(v.y, 0.0f) * u4.y
                     + fmaxf(v.z, 0.0f) * u4.z + fmaxf(v.w, 0.0f) * u4.w;
            float a2 = fmaxf(u.x, 0.0f) * p4.x + fmaxf(u.y, 0.0f) * p4.y
                     + fmaxf(u.z, 0.0f) * p4.z + fmaxf(u.w, 0.0f) * p4.w;
#pragma unroll
            for (int o = 16; o > 0; o >>= 1) {
                a1 += __shfl_xor_sync(0xFFFFFFFFu, a1, o);
                a2 += __shfl_xor_sync(0xFFFFFFFFu, a2, o);
            }
            if (lane == 0) { Trow[c] = a1; Tcol[c] = a2; }
        }
    }
    __syncthreads();

    const float4 bn = *(const float4*)&bbox[n * 4];
    const float4 bm = *(const float4*)&bbox[m * 4];
    const float wn = bn.z - bn.x, hn = bn.w - bn.y;
    const float wm = bm.z - bm.x, hm = bm.w - bm.y;
    const float xcn = 0.5f * (bn.x + bn.z), ycn = 0.5f * (bn.y + bn.w);
    const float xcm = 0.5f * (bm.x + bm.z), ycm = 0.5f * (bm.y + bm.w);

    const float dx1 = __fdividef(xcm - xcn, wn);
    const float dy1 = __fdividef(ycm - ycn, hn);
    const float dw1 = __logf(__fdividef(wm, wn));
    const float dh1 = __logf(__fdividef(hm, hn));
    const float dx2 = __fdividef(xcn - xcm, wm);
    const float dy2 = __fdividef(ycn - ycm, hm);
    const float dw2 = -dw1;
    const float dh2 = -dh1;

    float p1 = 0.0f, p2 = 0.0f;
#pragma unroll 8
    for (int d = 0; d < POSD; d++) {
        const float w0 = wpos_s[0][d], w1 = wpos_s[1][d],
                    w2 = wpos_s[2][d], w3 = wpos_s[3][d], wp = wp2[d];
        float t1 = dx1 * w0 + dy1 * w1 + dw1 * w2 + dh1 * w3;
        float t2 = dx2 * w0 + dy2 * w1 + dw2 * w2 + dh2 * w3;
        p1 += fmaxf(t1, 0.0f) * wp;
        p2 += fmaxf(t2, 0.0f) * wp;
    }

    const int cm = scls[m];
    const float r = fmaxf(fsig(Trow[cm] + p1) - fsig(Tcol[cm] + p2), 0.0f);
    g_rel[n * N_OBJ + m] = __float2half_rn(r);
}

// ============================================================================
// Kernel 2: main GEMM, K-pipelined staging + smem C-relayout epilogue.
// After GEMM: warps 0-3 STS acc (rows 0-63) into smA region, warps 4-7
// (rows 64-127) into smB region; then a fully-coalesced float4 epilogue.
// ============================================================================
__global__ void __launch_bounds__(256, 2)
main_kernel(const float* __restrict__ L, float* __restrict__ out)
{
    extern __shared__ __align__(128) char sm[];
    char* smA = sm;
    char* smB = sm + A_BYTES;

    const int tid  = threadIdx.x;
    const int wid  = tid >> 5;
    const int lane = tid & 31;
    const int P    = blockIdx.x * TP;

    const int s_row = tid >> 5;           // staging row 0..7
    const int s_p4  = tid & 31;           // float4 index within row

    // ---- prologue: stage A fully + B chunk 0 --------------------------------
    {
        const uint4* __restrict__ rr = (const uint4*)g_rel;   // 2048 uint4
#pragma unroll
        for (int e = 0; e < 8; e++) {
            int idx = tid + e * 256;
            int nn = idx >> 4, mq = idx & 15;
            *(uint4*)(smA + nn * ROWA + mq * 16) = rr[idx];
        }
        float4 b0 = *(const float4*)&L[(size_t)s_row * HW + P + s_p4 * 4];
        float4 b1 = *(const float4*)&L[(size_t)(s_row + 8) * HW + P + s_p4 * 4];
        uint2 s0, s1;
        s0.x = sig2_h2(b0.x, b0.y);  s0.y = sig2_h2(b0.z, b0.w);
        s1.x = sig2_h2(b1.x, b1.y);  s1.y = sig2_h2(b1.z, b1.w);
        *(uint2*)(smB + s_row * ROWB + s_p4 * 8) = s0;
        *(uint2*)(smB + (s_row + 8) * ROWB + s_p4 * 8) = s1;
    }
    __syncthreads();

    // ---- warp tiling: 2 n-groups x 4 p-groups; warp = n64 x p32 ------------
    const int nb = (wid >> 2) * 64;
    const int pb = (wid & 3) * 32;

    float acc[4][4][4];
#pragma unroll
    for (int a = 0; a < 4; a++)
#pragma unroll
        for (int b = 0; b < 4; b++)
#pragma unroll
            for (int q = 0; q < 4; q++) acc[a][b][q] = 0.0f;

    const int a_grp = lane >> 3;
    const int a_row = (a_grp & 1) * 8 + (lane & 7);
    const int a_col = (a_grp >> 1) * 8;
    const int b_row = lane & 15;

    const uint32_t uA = smem_u32(smA);
    const uint32_t uB = smem_u32(smB);

#pragma unroll
    for (int kc = 0; kc < 8; kc++) {
        // prefetch B chunk kc+1 (LDG latency hides under MMA kc)
        float4 pf0, pf1;
        if (kc < 7) {
            const int mb = (kc + 1) * 16;
            pf0 = *(const float4*)&L[(size_t)(mb + s_row) * HW + P + s_p4 * 4];
            pf1 = *(const float4*)&L[(size_t)(mb + 8 + s_row) * HW + P + s_p4 * 4];
        }

        const int k0 = kc * 16;
        uint32_t Af[4][4];
#pragma unroll
        for (int a = 0; a < 4; a++)
            ldmx4(Af[a], uA + (uint32_t)((nb + a * 16 + a_row) * ROWA + (k0 + a_col) * 2));
        uint32_t Bf[4][2];
#pragma unroll
        for (int b = 0; b < 4; b++)
            ldmx2t(Bf[b], uB + (uint32_t)((k0 + b_row) * ROWB + (pb + b * 8) * 2));
#pragma unroll
        for (int a = 0; a < 4; a++)
#pragma unroll
            for (int b = 0; b < 4; b++)
                mma_fp16(acc[a][b], Af[a], Bf[b]);

        if (kc < 7) {
            const int mb = (kc + 1) * 16;
            uint2 s0, s1;
            s0.x = sig2_h2(pf0.x, pf0.y);  s0.y = sig2_h2(pf0.z, pf0.w);
            s1.x = sig2_h2(pf1.x, pf1.y);  s1.y = sig2_h2(pf1.z, pf1.w);
            *(uint2*)(smB + (mb + s_row) * ROWB + s_p4 * 8) = s0;
            *(uint2*)(smB + (mb + 8 + s_row) * ROWB + s_p4 * 8) = s1;
            __syncthreads();
        }
    }

    // ---- C relayout: fragments -> smem (fp32, padded rows) -------------------
    __syncthreads();                       // all LDSM reads done before overwrite
    {
        char* smC = (nb == 0) ? smA : smB; // warps 0-3 rows 0-63; 4-7 rows 64-127
        const int g = lane >> 2, t4 = lane & 3;
#pragma unroll
        for (int a = 0; a < 4; a++) {
#pragma unroll
            for (int b = 0; b < 4; b++) {
                const int rr = a * 16 + g;            // local row 0..63
                const int pl = pb + b * 8 + 2 * t4;   // pixel 0..127 (even)
                float2 c01 = make_float2(acc[a][b][0], acc[a][b][1]);
                float2 c23 = make_float2(acc[a][b][2], acc[a][b][3]);
                *(float2*)(smC + rr * ROWC + pl * 4)       = c01;
                *(float2*)(smC + (rr + 8) * ROWC + pl * 4) = c23;
            }
        }
    }
    __syncthreads();

    // ---- coalesced epilogue: out = L * (1 - sigmoid(L) * w) ------------------
#pragma unroll
    for (int e = 0; e < 16; e++) {
        int idx = tid + e * 256;           // float4 index, 4096 total
        int r  = idx >> 5;                 // row 0..127
        int p4 = idx & 31;                 // float4 within row
        const char* smC = (r < 64) ? smA : smB;
        float4 w  = *(const float4*)(smC + (r & 63) * ROWC + p4 * 16);
        size_t off = (size_t)r * HW + P + p4 * 4;
        float4 l4 = *(const float4*)&L[off];
        float4 ov;
        ov.x = l4.x * (1.0f - fsig(l4.x) * w.x);
        ov.y = l4.y * (1.0f - fsig(l4.y) * w.y);
        ov.z = l4.z * (1.0f - fsig(l4.z) * w.z);
        ov.w = l4.w * (1.0f - fsig(l4.w) * w.w);
        *(float4*)&out[off] = ov;
    }
}

// ============================================================================
extern "C" void kernel_launch(void* const* d_in, const int* in_sizes, int n_in,
                              void* d_out, int out_size)
{
    const float* L     = (const float*)d_in[0];   // mask_logits (1,128,192,192)
    const float* bbox  = (const float*)d_in[1];   // (128,4)
    const float* W_U   = (const float*)d_in[2];   // (80,128)
    const float* W_V   = (const float*)d_in[3];   // (80,128)
    const float* W_pos = (const float*)d_in[4];   // (4,64)
    const float* W_P   = (const float*)d_in[5];   // (192,1)
    const int*   cls   = (const int*)d_in[6];     // (128,)
    float* out = (float*)d_out;

    const int dyn_smem = A_BYTES + B_BYTES;       // 69632 B -> 2 CTAs/SM
    cudaFuncSetAttribute(main_kernel,
                         cudaFuncAttributeMaxDynamicSharedMemorySize, dyn_smem);

    score_rel_kernel<<<N_OBJ, N_OBJ>>>(bbox, W_U, W_V, W_pos, W_P, cls);
    main_kernel<<<GRIDM, 256, dyn_smem>>>(L, out);
}

// round 14
// speedup vs baseline: 1.2888x; 1.1202x over previous
#include <cuda_runtime.h>
#include <cuda_fp16.h>
#include <math.h>
#include <stdint.h>

#define N_OBJ   128
#define HW      36864      // 192*192
#define CLSD    128
#define POSD    64
#define NCLS    80
#define TP      128        // pixels per block tile (main)
#define GRIDM   (HW / TP)  // 288 blocks; occ 2/SM -> 296 slots -> 1 wave
#define ROWA    272        // fp16 row stride bytes (17 x 16B -> LDSM conflict-free)
#define ROWB    272
#define ROWC    528        // fp32 C relayout row stride bytes (132 floats)
#define A_BYTES (128 * ROWA)   // 34816
#define B_BYTES (128 * ROWB)   // 34816

// -------- scratch (__device__ globals) --------------------------------------
__device__ __half g_rel[N_OBJ * N_OBJ];    // relation_score fp16, [n][m]

__device__ __forceinline__ float fsig(float x) {   // sigmoid via single MUFU
    float t;
    asm("tanh.approx.f32 %0, %1;" : "=f"(t) : "f"(0.5f * x));
    return fmaf(0.5f, t, 0.5f);
}
__device__ __forceinline__ uint32_t smem_u32(const void* p) {
    uint32_t a;
    asm("{ .reg .u64 t; cvta.to.shared.u64 t, %1; cvt.u32.u64 %0, t; }" : "=r"(a) : "l"(p));
    return a;
}
__device__ __forceinline__ void ldmx4(uint32_t r[4], uint32_t addr) {
    asm volatile("ldmatrix.sync.aligned.m8n8.x4.shared.b16 {%0,%1,%2,%3}, [%4];"
        : "=r"(r[0]), "=r"(r[1]), "=r"(r[2]), "=r"(r[3]) : "r"(addr));
}
__device__ __forceinline__ void ldmx4t(uint32_t r[4], uint32_t addr) {
    asm volatile("ldmatrix.sync.aligned.m8n8.x4.trans.shared.b16 {%0,%1,%2,%3}, [%4];"
        : "=r"(r[0]), "=r"(r[1]), "=r"(r[2]), "=r"(r[3]) : "r"(addr));
}
__device__ __forceinline__ void mma_fp16(float c[4], const uint32_t a[4], const uint32_t b[2]) {
    asm volatile(
        "mma.sync.aligned.m16n8k16.row.col.f32.f16.f16.f32 "
        "{%0,%1,%2,%3}, {%4,%5,%6,%7}, {%8,%9}, {%0,%1,%2,%3};"
        : "+f"(c[0]), "+f"(c[1]), "+f"(c[2]), "+f"(c[3])
        : "r"(a[0]), "r"(a[1]), "r"(a[2]), "r"(a[3]), "r"(b[0]), "r"(b[1]));
}
// sigmoid of 2 floats -> packed half2, single MUFU (f16x2 tanh)
__device__ __forceinline__ uint32_t sig2_h2(float x, float y) {
    __half2 h = __floats2half2_rn(0.5f * x, 0.5f * y);
    uint32_t hu = *(uint32_t*)&h, tu;
    asm("tanh.approx.f16x2 %0, %1;" : "=r"(tu) : "r"(hu));
    const __half2 c05 = __floats2half2_rn(0.5f, 0.5f);
    __half2 t = *(__half2*)&tu;
    __half2 r = __hfma2(t, c05, c05);
    return *(uint32_t*)&r;
}

// ============================================================================
// Kernel 1 (fused ttab + score + rel), 256 threads: 8 warps split phase-1.
// ============================================================================
__global__ void __launch_bounds__(256)
score_rel_kernel(const float* __restrict__ bbox,
                 const float* __restrict__ W_U,
                 const float* __restrict__ W_V,
                 const float* __restrict__ W_pos,
                 const float* __restrict__ W_P,
                 const int*   __restrict__ cls_idx)
{
    const int n    = blockIdx.x;
    const int tid  = threadIdx.x;
    const int wid  = tid >> 5;
    const int lane = tid & 31;

    __shared__ __align__(16) float uP[CLSD];
    __shared__ __align__(16) float pv[CLSD];
    __shared__ float Trow[NCLS];
    __shared__ float Tcol[NCLS];
    __shared__ float wpos_s[4][POSD];
    __shared__ float wp2[POSD];
    __shared__ int   scls[N_OBJ];

    const int cn = cls_idx[n] - 1;

    // ---- phase 0 (threads 0-127): stage per-block vectors -------------------
    if (tid < 128) {
        const int m = tid;
        const float wpk = W_P[m];
        uP[m] = fmaxf(W_U[cn * CLSD + m], 0.0f) * wpk;
        pv[m] = wpk * fmaxf(W_V[cn * CLSD + m], 0.0f);
        scls[m] = cls_idx[m] - 1;
        if (m < POSD) {
            wp2[m] = W_P[CLSD + m];
            wpos_s[0][m] = W_pos[0 * POSD + m];
            wpos_s[1][m] = W_pos[1 * POSD + m];
            wpos_s[2][m] = W_pos[2 * POSD + m];
            wpos_s[3][m] = W_pos[3 * POSD + m];
        }
    }
    __syncthreads();

    // ---- phase 1: Trow / Tcol (8 warps x 10 classes) ------------------------
    {
        const float4 u4 = *(const float4*)&uP[lane * 4];
        const float4 p4 = *(const float4*)&pv[lane * 4];
#pragma unroll
        for (int it = 0; it < NCLS / 8; it++) {
            const int c = wid * (NCLS / 8) + it;
            float4 v = *(const float4*)&W_V[c * CLSD + lane * 4];
            float4 u = *(const float4*)&W_U[c * CLSD + lane * 4];
            float a1 = fmaxf(v.x, 0.0f) * u4.x + fmaxf(v.y, 0.0f) * u4.y
                     + fmaxf(v.z, 0.0f) * u4.z + fmaxf(v.w, 0.0f) * u4.w;
            float a2 = fmaxf(u.x, 0.0f) * p4.x + fmaxf(u.y, 0.0f) * p4.y
                     + fmaxf(u.z, 0.0f) * p4.z + fmaxf(u.w, 0.0f) * p4.w;
#pragma unroll
            for (int o = 16; o > 0; o >>= 1) {
                a1 += __shfl_xor_sync(0xFFFFFFFFu, a1, o);
                a2 += __shfl_xor_sync(0xFFFFFFFFu, a2, o);
            }
            if (lane == 0) { Trow[c] = a1; Tcol[c] = a2; }
        }
    }
    __syncthreads();

    // ---- phase 2 (threads 0-127): score both directions + rel ---------------
    if (tid < 128) {
        const int m = tid;
        const float4 bn = *(const float4*)&bbox[n * 4];
        const float4 bm = *(const float4*)&bbox[m * 4];
        const float wn = bn.z - bn.x, hn = bn.w - bn.y;
        const float wm = bm.z - bm.x, hm = bm.w - bm.y;
        const float xcn = 0.5f * (bn.x + bn.z), ycn = 0.5f * (bn.y + bn.w);
        const float xcm = 0.5f * (bm.x + bm.z), ycm = 0.5f * (bm.y + bm.w);

        const float dx1 = __fdividef(xcm - xcn, wn);
        const float dy1 = __fdividef(ycm - ycn, hn);
        const float dw1 = __logf(__fdividef(wm, wn));
        const float dh1 = __logf(__fdividef(hm, hn));
        const float dx2 = __fdividef(xcn - xcm, wm);
        const float dy2 = __fdividef(ycn - ycm, hm);
        const float dw2 = -dw1;
        const float dh2 = -dh1;

        float p1 = 0.0f, p2 = 0.0f;
#pragma unroll 8
        for (int d = 0; d < POSD; d++) {
            const float w0 = wpos_s[0][d], w1 = wpos_s[1][d],
                        w2 = wpos_s[2][d], w3 = wpos_s[3][d], wp = wp2[d];
            float t1 = dx1 * w0 + dy1 * w1 + dw1 * w2 + dh1 * w3;
            float t2 = dx2 * w0 + dy2 * w1 + dw2 * w2 + dh2 * w3;
            p1 += fmaxf(t1, 0.0f) * wp;
            p2 += fmaxf(t2, 0.0f) * wp;
        }

        const int cm = scls[m];
        const float r = fmaxf(fsig(Trow[cm] + p1) - fsig(Tcol[cm] + p2), 0.0f);
        g_rel[n * N_OBJ + m] = __float2half_rn(r);
    }
}

// ============================================================================
// Kernel 2: main GEMM, K-pipelined staging + ldmx4t B loads + smem C-relayout.
// ============================================================================
__global__ void __launch_bounds__(256, 2)
main_kernel(const float* __restrict__ L, float* __restrict__ out)
{
    extern __shared__ __align__(128) char sm[];
    char* smA = sm;
    char* smB = sm + A_BYTES;

    const int tid  = threadIdx.x;
    const int wid  = tid >> 5;
    const int lane = tid & 31;
    const int P    = blockIdx.x * TP;

    const int s_row = tid >> 5;           // staging row 0..7
    const int s_p4  = tid & 31;           // float4 index within row

    // ---- prologue: stage A fully + B chunk 0 --------------------------------
    {
        const uint4* __restrict__ rr = (const uint4*)g_rel;   // 2048 uint4
#pragma unroll
        for (int e = 0; e < 8; e++) {
            int idx = tid + e * 256;
            int nn = idx >> 4, mq = idx & 15;
            *(uint4*)(smA + nn * ROWA + mq * 16) = rr[idx];
        }
        float4 b0 = *(const float4*)&L[(size_t)s_row * HW + P + s_p4 * 4];
        float4 b1 = *(const float4*)&L[(size_t)(s_row + 8) * HW + P + s_p4 * 4];
        uint2 s0, s1;
        s0.x = sig2_h2(b0.x, b0.y);  s0.y = sig2_h2(b0.z, b0.w);
        s1.x = sig2_h2(b1.x, b1.y);  s1.y = sig2_h2(b1.z, b1.w);
        *(uint2*)(smB + s_row * ROWB + s_p4 * 8) = s0;
        *(uint2*)(smB + (s_row + 8) * ROWB + s_p4 * 8) = s1;
    }
    __syncthreads();

    // ---- warp tiling: 2 n-groups x 4 p-groups; warp = n64 x p32 ------------
    const int nb = (wid >> 2) * 64;
    const int pb = (wid & 3) * 32;

    float acc[4][4][4];
#pragma unroll
    for (int a = 0; a < 4; a++)
#pragma unroll
        for (int b = 0; b < 4; b++)
#pragma unroll
            for (int q = 0; q < 4; q++) acc[a][b][q] = 0.0f;

    const int a_grp = lane >> 3;
    const int a_row = (a_grp & 1) * 8 + (lane & 7);
    const int a_col = (a_grp >> 1) * 8;
    // ldmx4t lane addressing: lanes 0-15 -> rows k0+(lane&15) pixel group 2b,
    // lanes 16-31 -> same rows, pixel group 2b+1
    const int bt_row = lane & 15;
    const int bt_col = (lane >> 4) << 3;  // 0 or 8

    const uint32_t uA = smem_u32(smA);
    const uint32_t uB = smem_u32(smB);

#pragma unroll
    for (int kc = 0; kc < 8; kc++) {
        // prefetch B chunk kc+1 (LDG latency hides under MMA kc)
        float4 pf0, pf1;
        if (kc < 7) {
            const int mb = (kc + 1) * 16;
            pf0 = *(const float4*)&L[(size_t)(mb + s_row) * HW + P + s_p4 * 4];
            pf1 = *(const float4*)&L[(size_t)(mb + 8 + s_row) * HW + P + s_p4 * 4];
        }

        const int k0 = kc * 16;
        uint32_t Af[4][4];
#pragma unroll
        for (int a = 0; a < 4; a++)
            ldmx4(Af[a], uA + (uint32_t)((nb + a * 16 + a_row) * ROWA + (k0 + a_col) * 2));
        uint32_t Bf[4][2];
#pragma unroll
        for (int bb = 0; bb < 2; bb++) {
            uint32_t r[4];
            ldmx4t(r, uB + (uint32_t)((k0 + bt_row) * ROWB
                                      + (pb + bb * 16 + bt_col) * 2));
            Bf[2 * bb][0]     = r[0];  Bf[2 * bb][1]     = r[1];
            Bf[2 * bb + 1][0] = r[2];  Bf[2 * bb + 1][1] = r[3];
        }
#pragma unroll
        for (int a = 0; a < 4; a++)
#pragma unroll
            for (int b = 0; b < 4; b++)
                mma_fp16(acc[a][b], Af[a], Bf[b]);

        if (kc < 7) {
            const int mb = (kc + 1) * 16;
            uint2 s0, s1;
            s0.x = sig2_h2(pf0.x, pf0.y);  s0.y = sig2_h2(pf0.z, pf0.w);
            s1.x = sig2_h2(pf1.x, pf1.y);  s1.y = sig2_h2(pf1.z, pf1.w);
            *(uint2*)(smB + (mb + s_row) * ROWB + s_p4 * 8) = s0;
            *(uint2*)(smB + (mb + 8 + s_row) * ROWB + s_p4 * 8) = s1;
            __syncthreads();
        }
    }

    // ---- C relayout: fragments -> smem (fp32, padded rows) -------------------
    __syncthreads();                       // all LDSM reads done before overwrite
    {
        char* smC = (nb == 0) ? smA : smB; // warps 0-3 rows 0-63; 4-7 rows 64-127
        const int g = lane >> 2, t4 = lane & 3;
#pragma unroll
        for (int a = 0; a < 4; a++) {
#pragma unroll
            for (int b = 0; b < 4; b++) {
                const int rr = a * 16 + g;            // local row 0..63
                const int pl = pb + b * 8 + 2 * t4;   // pixel 0..127 (even)
                float2 c01 = make_float2(acc[a][b][0], acc[a][b][1]);
                float2 c23 = make_float2(acc[a][b][2], acc[a][b][3]);
                *(float2*)(smC + rr * ROWC + pl * 4)       = c01;
                *(float2*)(smC + (rr + 8) * ROWC + pl * 4) = c23;
            }
        }
    }
    __syncthreads();

    // ---- coalesced epilogue: out = L * (1 - sigmoid(L) * w) ------------------
#pragma unroll
    for (int e = 0; e < 16; e++) {
        int idx = tid + e * 256;           // float4 index, 4096 total
        int r  = idx >> 5;                 // row 0..127
        int p4 = idx & 31;                 // float4 within row
        const char* smC = (r < 64) ? smA : smB;
        float4 w  = *(const float4*)(smC + (r & 63) * ROWC + p4 * 16);
        size_t off = (size_t)r * HW + P + p4 * 4;
        float4 l4 = *(const float4*)&L[off];
        float4 ov;
        ov.x = l4.x * (1.0f - fsig(l4.x) * w.x);
        ov.y = l4.y * (1.0f - fsig(l4.y) * w.y);
        ov.z = l4.z * (1.0f - fsig(l4.z) * w.z);
        ov.w = l4.w * (1.0f - fsig(l4.w) * w.w);
        *(float4*)&out[off] = ov;
    }
}

// ============================================================================
extern "C" void kernel_launch(void* const* d_in, const int* in_sizes, int n_in,
                              void* d_out, int out_size)
{
    const float* L     = (const float*)d_in[0];   // mask_logits (1,128,192,192)
    const float* bbox  = (const float*)d_in[1];   // (128,4)
    const float* W_U   = (const float*)d_in[2];   // (80,128)
    const float* W_V   = (const float*)d_in[3];   // (80,128)
    const float* W_pos = (const float*)d_in[4];   // (4,64)
    const float* W_P   = (const float*)d_in[5];   // (192,1)
    const int*   cls   = (const int*)d_in[6];     // (128,)
    float* out = (float*)d_out;

    const int dyn_smem = A_BYTES + B_BYTES;       // 69632 B -> 2 CTAs/SM
    cudaFuncSetAttribute(main_kernel,
                         cudaFuncAttributeMaxDynamicSharedMemorySize, dyn_smem);

    score_rel_kernel<<<N_OBJ, 256>>>(bbox, W_U, W_V, W_pos, W_P, cls);
    main_kernel<<<GRIDM, 256, dyn_smem>>>(L, out);
}